// round 5
// baseline (speedup 1.0000x reference)
#include <cuda_runtime.h>
#include <math.h>

#define NN     96
#define INDIM  64
#define HID    256
#define ZDIM   64
#define TRIN   4656
#define NB     8            // CTAs (one cluster)
#define NT     1024
#define RPB    12           // rows per CTA
#define ITERS  50
#define RENORM 5
#define NSLOT  (ITERS / RENORM)
#define QPITCH 100          // floats; 25 float4 -> conflict-free LDS.128
#define DPER   (TRIN / NB)  // 582 dec2 outputs per CTA

// ------------- persistent device scratch (no allocations allowed) -------------
__device__ int   g_cnt[NN * NN];
__device__ float g_dis[NN];
__device__ float g_degA[NN];
__device__ float g_tmp1[NN * HID];
__device__ float g_tmp2[NN * HID];
__device__ float g_h[NN * HID];
__device__ float g_gvec[HID];
__device__ float g_d1[HID];
__device__ float g_kl;
__device__ float g_vecb[TRIN];
__device__ float g_B[NN * NN];
__device__ float g_Bd[NN];
__device__ float g_degB[NN];
__device__ float g_rec[NB];
__device__ float g_part[NSLOT * NB];
__device__ float g_M[2 * NN * NN];     // ping-pong max-message matrix

// hardware cluster barrier (~380-490cyc, flushes L1D, release/acquire semantics)
__device__ __forceinline__ void csync() {
    asm volatile("barrier.cluster.arrive.aligned;\n\t"
                 "barrier.cluster.wait.aligned;" ::: "memory");
}

__device__ __forceinline__ float blk_sum(float v, volatile float* sr) {
    int t = threadIdx.x;
    #pragma unroll
    for (int o = 16; o; o >>= 1) v += __shfl_down_sync(0xFFFFFFFFu, v, o);
    __syncthreads();
    if ((t & 31) == 0) sr[t >> 5] = v;
    __syncthreads();
    if (t < 32) {
        float x = sr[t];
        #pragma unroll
        for (int o = 16; o; o >>= 1) x += __shfl_down_sync(0xFFFFFFFFu, x, o);
        if (t == 0) sr[32] = x;
    }
    __syncthreads();
    return sr[32];
}

extern "C" __global__ void __launch_bounds__(NT, 1) __cluster_dims__(NB, 1, 1)
gvae_kernel(const float* __restrict__ X, const int* __restrict__ EI, int E,
            const float* __restrict__ A,
            const float* __restrict__ W1, const float* __restrict__ B1,
            const float* __restrict__ G1, const float* __restrict__ BB1,
            const float* __restrict__ W2, const float* __restrict__ B2,
            const float* __restrict__ G2, const float* __restrict__ BB2,
            const float* __restrict__ MUW, const float* __restrict__ MUB,
            const float* __restrict__ LVW, const float* __restrict__ LVB,
            const float* __restrict__ D1W, const float* __restrict__ D1B,
            const float* __restrict__ D2W, const float* __restrict__ D2B,
            const float* __restrict__ EPS, float* __restrict__ OUT, int osz)
{
    const int bid = blockIdx.x, tid = threadIdx.x;
    const int R0  = bid * RPB;
    const int wrp = tid >> 5, lane = tid & 31;

    __shared__ __align__(16) float uf[NN * QPITCH];   // 9600 floats: Q / front-end union
    __shared__ __align__(16) float s_x[RPB * NN];     // MPM state rows
    __shared__ int   s_nbr[RPB * 48];
    __shared__ int   s_nnb[RPB];
    __shared__ volatile float s_red[33];
    __shared__ float s_dpart[36];

    // ---- S0: zero edge-count matrix ----
    for (int p = bid * NT + tid; p < NN * NN; p += NB * NT) g_cnt[p] = 0;
    csync();

    // ---- S1: scatter edges + self loops; rowmm1 (x @ W1) for own rows ----
    for (int e = bid * NT + tid; e < E; e += NB * NT) {
        int s = EI[e], d = EI[E + e];
        atomicAdd(&g_cnt[d * NN + s], 1);
    }
    if (bid == 0 && tid < NN) atomicAdd(&g_cnt[tid * NN + tid], 1);
    {
        float* s_xin = uf;                            // [RPB][INDIM]
        if (tid < RPB * INDIM) s_xin[tid] = X[R0 * INDIM + tid];
        __syncthreads();
        for (int o = tid; o < RPB * HID; o += NT) {
            int r = o / HID, f = o % HID;
            const float* xr = s_xin + r * INDIM;
            float a0 = 0.f, a1 = 0.f;
            #pragma unroll 8
            for (int k = 0; k < INDIM; k += 2) {
                a0 += xr[k]     * W1[k * HID + f];
                a1 += xr[k + 1] * W1[(k + 1) * HID + f];
            }
            g_tmp1[(R0 + r) * HID + f] = a0 + a1;
        }
    }
    csync();

    // ---- S2: degrees -> dis; degA ----
    if (wrp < RPB) {
        int n = R0 + wrp;
        float dg = (float)__ldcg(&g_cnt[n * NN + lane])
                 + (float)__ldcg(&g_cnt[n * NN + lane + 32])
                 + (float)__ldcg(&g_cnt[n * NN + lane + 64]);
        #pragma unroll
        for (int o = 16; o; o >>= 1) dg += __shfl_down_sync(0xFFFFFFFFu, dg, o);
        if (lane == 0) g_dis[n] = rsqrtf(dg);
    } else if (wrp < 2 * RPB) {
        int n = R0 + (wrp - RPB);
        float dA = A[n * NN + lane] + A[n * NN + lane + 32] + A[n * NN + lane + 64];
        #pragma unroll
        for (int o = 16; o; o >>= 1) dA += __shfl_down_sync(0xFFFFFFFFu, dA, o);
        if (lane == 0) g_degA[n] = dA;
    }
    csync();

    // ---- S3: An rows + agg1 ----
    {
        float* s_An = uf + 4096;                      // [RPB][NN]
        for (int p = tid; p < RPB * NN; p += NT) {
            int r = p / NN, s = p % NN;
            s_An[p] = __ldcg(&g_dis[R0 + r]) * __ldcg(&g_dis[s])
                    * (float)__ldcg(&g_cnt[(R0 + r) * NN + s]);
        }
        __syncthreads();
        if (tid < RPB * (HID / 4)) {
            int r = tid / (HID / 4), f4 = tid % (HID / 4);
            const float4* t14 = (const float4*)g_tmp1;
            const float4* b14 = (const float4*)B1;
            float4 acc = b14[f4];
            const float* anr = s_An + r * NN;
            #pragma unroll 4
            for (int s = 0; s < NN; s++) {
                float an = anr[s];
                float4 tv = __ldcg(&t14[s * (HID / 4) + f4]);
                acc.x += an * tv.x; acc.y += an * tv.y;
                acc.z += an * tv.z; acc.w += an * tv.w;
            }
            ((float4*)g_tmp2)[(R0 + r) * (HID / 4) + f4] = acc;
        }
    }
    csync();

    // ---- S4: BN1 + relu (feature per warp) ----
    {
        int f = bid * 32 + wrp;
        float v0 = __ldcg(&g_tmp2[lane * HID + f]);
        float v1 = __ldcg(&g_tmp2[(lane + 32) * HID + f]);
        float v2 = __ldcg(&g_tmp2[(lane + 64) * HID + f]);
        float s = v0 + v1 + v2;
        #pragma unroll
        for (int o = 16; o; o >>= 1) s += __shfl_xor_sync(0xFFFFFFFFu, s, o);
        float m = s * (1.0f / NN);
        float d0 = v0 - m, d1 = v1 - m, d2 = v2 - m;
        float vv = d0 * d0 + d1 * d1 + d2 * d2;
        #pragma unroll
        for (int o = 16; o; o >>= 1) vv += __shfl_xor_sync(0xFFFFFFFFu, vv, o);
        float sc = G1[f] * rsqrtf(vv * (1.0f / NN) + 1e-5f);
        float bb = BB1[f];
        g_h[lane * HID + f]        = fmaxf(d0 * sc + bb, 0.f);
        g_h[(lane + 32) * HID + f] = fmaxf(d1 * sc + bb, 0.f);
        g_h[(lane + 64) * HID + f] = fmaxf(d2 * sc + bb, 0.f);
    }
    csync();

    // ---- S5: rowmm2 ----
    {
        float* s_h = uf;                              // [RPB][HID]
        for (int p = tid; p < RPB * HID; p += NT) s_h[p] = __ldcg(&g_h[R0 * HID + p]);
        __syncthreads();
        for (int o = tid; o < RPB * HID; o += NT) {
            int r = o / HID, f = o % HID;
            const float* hr = s_h + r * HID;
            float a0 = 0.f, a1 = 0.f;
            #pragma unroll 8
            for (int k = 0; k < HID; k += 2) {
                a0 += hr[k]     * W2[k * HID + f];
                a1 += hr[k + 1] * W2[(k + 1) * HID + f];
            }
            g_tmp1[(R0 + r) * HID + f] = a0 + a1;
        }
    }
    csync();

    // ---- S6: agg2 (reuses s_An) ----
    if (tid < RPB * (HID / 4)) {
        const float* s_An = uf + 4096;
        int r = tid / (HID / 4), f4 = tid % (HID / 4);
        const float4* t14 = (const float4*)g_tmp1;
        const float4* b24 = (const float4*)B2;
        float4 acc = b24[f4];
        const float* anr = s_An + r * NN;
        #pragma unroll 4
        for (int s = 0; s < NN; s++) {
            float an = anr[s];
            float4 tv = __ldcg(&t14[s * (HID / 4) + f4]);
            acc.x += an * tv.x; acc.y += an * tv.y;
            acc.z += an * tv.z; acc.w += an * tv.w;
        }
        ((float4*)g_tmp2)[(R0 + r) * (HID / 4) + f4] = acc;
    }
    csync();

    // ---- S7: BN2 + relu + fused sum-pool ----
    {
        int f = bid * 32 + wrp;
        float v0 = __ldcg(&g_tmp2[lane * HID + f]);
        float v1 = __ldcg(&g_tmp2[(lane + 32) * HID + f]);
        float v2 = __ldcg(&g_tmp2[(lane + 64) * HID + f]);
        float s = v0 + v1 + v2;
        #pragma unroll
        for (int o = 16; o; o >>= 1) s += __shfl_xor_sync(0xFFFFFFFFu, s, o);
        float m = s * (1.0f / NN);
        float d0 = v0 - m, d1 = v1 - m, d2 = v2 - m;
        float vv = d0 * d0 + d1 * d1 + d2 * d2;
        #pragma unroll
        for (int o = 16; o; o >>= 1) vv += __shfl_xor_sync(0xFFFFFFFFu, vv, o);
        float sc = G2[f] * rsqrtf(vv * (1.0f / NN) + 1e-5f);
        float bb = BB2[f];
        float h0 = fmaxf(d0 * sc + bb, 0.f);
        float h1 = fmaxf(d1 * sc + bb, 0.f);
        float h2 = fmaxf(d2 * sc + bb, 0.f);
        g_h[lane * HID + f]        = h0;
        g_h[(lane + 32) * HID + f] = h1;
        g_h[(lane + 64) * HID + f] = h2;
        float ps = h0 + h1 + h2;
        #pragma unroll
        for (int o = 16; o; o >>= 1) ps += __shfl_down_sync(0xFFFFFFFFu, ps, o);
        if (lane == 0) g_gvec[f] = ps;
    }
    csync();

    // ---- S8: VAE head + dec1 (CTA 0) ----
    if (bid == 0) {
        float* s_g = uf;                              // 256
        float* s_z = uf + 256;                        // 64
        if (tid < HID) s_g[tid] = __ldcg(&g_gvec[tid]);
        __syncthreads();
        float klt = 0.f;
        if (tid < ZDIM) {
            float mu = MUB[tid], lv = LVB[tid];
            #pragma unroll 4
            for (int k = 0; k < HID; k++) {
                float gv = s_g[k];
                mu += gv * MUW[k * ZDIM + tid];
                lv += gv * LVW[k * ZDIM + tid];
            }
            s_z[tid] = mu + EPS[tid] * expf(0.5f * lv);
            klt = 1.f + lv - mu * mu - expf(lv);
        }
        float ks = blk_sum(klt, s_red);
        if (tid == 0) g_kl = -0.5f * ks * (1.0f / ZDIM);
        __syncthreads();
        if (tid < HID) {
            float acc = D1B[tid];
            #pragma unroll
            for (int k = 0; k < ZDIM; k++) acc += s_z[k] * D1W[k * HID + tid];
            g_d1[tid] = fmaxf(acc, 0.f);
        }
    }
    csync();

    // ---- S9: dec2 (582 outputs per CTA, streams 4.8MB) ----
    {
        float* s_d1 = uf;
        if (tid < HID) s_d1[tid] = __ldcg(&g_d1[tid]);
        __syncthreads();
        int o = bid * DPER + tid;
        if (tid < DPER) {
            float a0 = 0.f, a1 = 0.f, a2 = 0.f, a3 = 0.f;
            #pragma unroll 4
            for (int k = 0; k < HID; k += 4) {
                a0 += s_d1[k]     * D2W[k * TRIN + o];
                a1 += s_d1[k + 1] * D2W[(k + 1) * TRIN + o];
                a2 += s_d1[k + 2] * D2W[(k + 2) * TRIN + o];
                a3 += s_d1[k + 3] * D2W[(k + 3) * TRIN + o];
            }
            g_vecb[o] = D2B[o] + ((a0 + a1) + (a2 + a3));
        }
    }
    csync();

    // ---- S10: build B, Bd, degB, BCE partials ----
    {
        float rc = 0.f;
        float Bv1, Bv2 = 0.f;
        {
            int r = tid / NN, m = tid % NN, n = R0 + r;
            int i_ = n < m ? n : m, j_ = n < m ? m : n;
            int o = i_ * NN - (i_ * (i_ - 1)) / 2 + (j_ - i_);
            float v = __ldcg(&g_vecb[o]);
            Bv1 = 1.f / (1.f + expf(-v));
            g_B[n * NN + m] = Bv1;
            if (m == n) g_Bd[n] = Bv1;
            if (m >= n) rc += fmaxf(v, 0.f) - v * A[n * NN + m] + log1pf(expf(-fabsf(v)));
        }
        if (tid < 128) {
            int p2 = tid + NT;
            int r = p2 / NN, m = p2 % NN, n = R0 + r;
            int i_ = n < m ? n : m, j_ = n < m ? m : n;
            int o = i_ * NN - (i_ * (i_ - 1)) / 2 + (j_ - i_);
            float v = __ldcg(&g_vecb[o]);
            Bv2 = 1.f / (1.f + expf(-v));
            g_B[n * NN + m] = Bv2;
            if (m == n) g_Bd[n] = Bv2;
            if (m >= n) rc += fmaxf(v, 0.f) - v * A[n * NN + m] + log1pf(expf(-fabsf(v)));
        }
        float p1 = Bv1;
        #pragma unroll
        for (int o = 16; o; o >>= 1) p1 += __shfl_down_sync(0xFFFFFFFFu, p1, o);
        if (lane == 0) s_dpart[wrp] = p1;
        if (wrp < 4) {
            float p2s = Bv2;
            #pragma unroll
            for (int o = 16; o; o >>= 1) p2s += __shfl_down_sync(0xFFFFFFFFu, p2s, o);
            if (lane == 0) s_dpart[32 + wrp] = p2s;
        }
        __syncthreads();
        if (tid < RPB)
            g_degB[R0 + tid] = s_dpart[3 * tid] + s_dpart[3 * tid + 1] + s_dpart[3 * tid + 2];
        float rs = blk_sum(rc, s_red);
        if (tid == 0) g_rec[bid] = rs;
    }
    csync();

    // ---- MPM setup: Q -> SMEM (pitch 100), neighbor lists, D regs, x init ----
    for (int p = tid; p < NN * NN; p += NT) {
        int a = p / NN, b = p % NN;
        float q = (a == b) ? 0.f
                : __ldcg(&g_B[p]) * __ldcg(&g_Bd[a]) * __ldcg(&g_Bd[b]);
        uf[a * QPITCH + b] = q;
    }
    if (wrp < RPB) {
        int n = R0 + wrp, cnt = 0;
        #pragma unroll
        for (int seg = 0; seg < 3; seg++) {
            int m = seg * 32 + lane;
            bool pr = (m != n) && (A[n * NN + m] != 0.f);
            unsigned bal = __ballot_sync(0xFFFFFFFFu, pr);
            if (pr) s_nbr[wrp * 48 + cnt + __popc(bal & ((1u << lane) - 1u))] = m;
            cnt += __popc(bal);
        }
        if (lane == 0) s_nnb[wrp] = cnt;
    }
    float Dv, Dv2 = 0.f;
    {
        int r = tid / NN, a = tid % NN, n = R0 + r;
        Dv = A[n * NN + n] * __ldcg(&g_Bd[a])
           / (fabsf(__ldcg(&g_degA[n]) - __ldcg(&g_degB[a])) + 1.f);
        if (tid < 128) {
            int p2 = tid + NT; r = p2 / NN; a = p2 % NN; n = R0 + r;
            Dv2 = A[n * NN + n] * __ldcg(&g_Bd[a])
                / (fabsf(__ldcg(&g_degA[n]) - __ldcg(&g_degB[a])) + 1.f);
        }
    }
    for (int p = tid; p < RPB * NN; p += NT) s_x[p] = 1.0f / (float)NN;
    __syncthreads();

    // ---- MPM: 1 cluster.sync per iter (ping-pong M); renorm every 5 iters ----
    const float4* Q4 = (const float4*)uf;             // pitch 25 float4
    const float4* x4 = (const float4*)s_x;            // row pitch 24 float4
    const int aa = tid % NN, gg = tid / NN;           // gg < 10 valid for tid < 960

    for (int k = 0; k < ITERS; k++) {
        float* Mb = g_M + (k & 1) * (NN * NN);
        // phase A: M[i,a] = max_b Q[a,b] * x[i,b] for owned rows
        if (tid < 960) {
            const float4* qr  = Q4 + aa * (QPITCH / 4);
            const float4* xr0 = x4 + gg * (NN / 4);
            float m0 = 0.f, m1 = 0.f;
            if (gg < 2) {
                const float4* xr1 = x4 + (gg + 10) * (NN / 4);
                #pragma unroll
                for (int b = 0; b < NN / 4; b++) {
                    float4 qv = qr[b], v0 = xr0[b], v1 = xr1[b];
                    m0 = fmaxf(m0, fmaxf(fmaxf(qv.x * v0.x, qv.y * v0.y),
                                         fmaxf(qv.z * v0.z, qv.w * v0.w)));
                    m1 = fmaxf(m1, fmaxf(fmaxf(qv.x * v1.x, qv.y * v1.y),
                                         fmaxf(qv.z * v1.z, qv.w * v1.w)));
                }
                Mb[(R0 + gg + 10) * NN + aa] = m1;
            } else {
                #pragma unroll
                for (int b = 0; b < NN / 4; b++) {
                    float4 qv = qr[b], v0 = xr0[b];
                    m0 = fmaxf(m0, fmaxf(fmaxf(qv.x * v0.x, qv.y * v0.y),
                                         fmaxf(qv.z * v0.z, qv.w * v0.w)));
                }
            }
            Mb[(R0 + gg) * NN + aa] = m0;
        }
        csync();

        // phase B: xn = x*D + sum_{j in N(i)} M[j,a]
        float msg = 0.f;
        {
            int r = tid / NN, a = tid % NN;
            int nb = s_nnb[r];
            const int* nl = s_nbr + r * 48;
            int j = 0;
            for (; j + 4 <= nb; j += 4) {
                msg += __ldcg(&Mb[nl[j] * NN + a]) + __ldcg(&Mb[nl[j + 1] * NN + a])
                     + __ldcg(&Mb[nl[j + 2] * NN + a]) + __ldcg(&Mb[nl[j + 3] * NN + a]);
            }
            for (; j < nb; j++) msg += __ldcg(&Mb[nl[j] * NN + a]);
        }
        float xn = s_x[tid] * Dv + msg;
        float xn2 = 0.f;
        if (tid < 128) {
            int p2 = tid + NT, r = p2 / NN, a = p2 % NN;
            int nb = s_nnb[r];
            const int* nl = s_nbr + r * 48;
            float m2 = 0.f;
            int j = 0;
            for (; j + 4 <= nb; j += 4) {
                m2 += __ldcg(&Mb[nl[j] * NN + a]) + __ldcg(&Mb[nl[j + 1] * NN + a])
                    + __ldcg(&Mb[nl[j + 2] * NN + a]) + __ldcg(&Mb[nl[j + 3] * NN + a]);
            }
            for (; j < nb; j++) m2 += __ldcg(&Mb[nl[j] * NN + a]);
            xn2 = s_x[p2] * Dv2 + m2;
        }

        if (((k + 1) % RENORM) == 0) {
            float tot = blk_sum(xn * xn + xn2 * xn2, s_red);
            int slot = k / RENORM;
            if (tid == 0) g_part[slot * NB + bid] = tot;
            csync();
            float s2 = 0.f;
            #pragma unroll
            for (int c = 0; c < NB; c++) s2 += __ldcg(&g_part[slot * NB + c]);
            float invn = rsqrtf(s2);
            if (k == ITERS - 1) {
                int off = (osz > NN * NN) ? (osz - NN * NN) : 0;
                if (osz >= NN * NN) {
                    OUT[off + (R0 + tid / NN) * NN + (tid % NN)] = xn * invn;
                    if (tid < 128) {
                        int p2 = tid + NT;
                        OUT[off + (R0 + p2 / NN) * NN + (p2 % NN)] = xn2 * invn;
                    }
                }
                if (bid == 0 && tid == 0 && (osz < NN * NN || off > 0)) {
                    float rs = 0.f;
                    #pragma unroll
                    for (int c = 0; c < NB; c++) rs += __ldcg(&g_rec[c]);
                    OUT[0] = rs * (1.0f / (float)TRIN) + __ldcg(&g_kl);
                }
                return;
            }
            xn *= invn; xn2 *= invn;
        }
        s_x[tid] = xn;
        if (tid < 128) s_x[tid + NT] = xn2;
        __syncthreads();
    }
}

extern "C" void kernel_launch(void* const* d_in, const int* in_sizes, int n_in,
                              void* d_out, int out_size) {
    const float* X   = (const float*)d_in[0];
    const int*   EI  = (const int*)  d_in[1];
    const float* A   = (const float*)d_in[3];
    const float* W1  = (const float*)d_in[4];
    const float* B1  = (const float*)d_in[5];
    const float* G1  = (const float*)d_in[6];
    const float* BB1 = (const float*)d_in[7];
    const float* W2  = (const float*)d_in[8];
    const float* B2  = (const float*)d_in[9];
    const float* G2  = (const float*)d_in[10];
    const float* BB2 = (const float*)d_in[11];
    const float* MUW = (const float*)d_in[12];
    const float* MUB = (const float*)d_in[13];
    const float* LVW = (const float*)d_in[14];
    const float* LVB = (const float*)d_in[15];
    const float* D1W = (const float*)d_in[16];
    const float* D1B = (const float*)d_in[17];
    const float* D2W = (const float*)d_in[18];
    const float* D2B = (const float*)d_in[19];
    const float* EPS = (const float*)d_in[20];
    int E = in_sizes[1] / 2;

    gvae_kernel<<<NB, NT>>>(X, EI, E, A, W1, B1, G1, BB1, W2, B2, G2, BB2,
                            MUW, MUB, LVW, LVB, D1W, D1B, D2W, D2B, EPS,
                            (float*)d_out, out_size);
}

// round 7
// speedup vs baseline: 1.1489x; 1.1489x over previous
#include <cuda_runtime.h>
#include <math.h>

#define NN     96
#define INDIM  64
#define HID    256
#define ZDIM   64
#define TRIN   4656
#define NB     8
#define NT     384
#define RPB    12
#define ITERS  50
#define NSLOT  10

// ------------- persistent device scratch (no allocations allowed) -------------
__device__ int   g_cnt[NN * NN];
__device__ float g_dis[NN];
__device__ float g_degA[NN];
__device__ float g_tmp1[NN * HID];
__device__ float g_tmp2T[HID * NN];     // transposed: feature-major
__device__ float g_h[NN * HID];
__device__ float g_gvec[HID];
__device__ float g_d1[HID];
__device__ float g_kl;
__device__ __align__(16) float g_vecb[TRIN];
__device__ float g_B[NN * NN];
__device__ float g_Bd[NN];
__device__ float g_degB[NN];
__device__ float g_rec[NB];
__device__ float g_part[NSLOT * NB];
__device__ float g_M[2 * NN * NN];      // ping-pong max-message matrix

// hardware cluster barrier (flushes L1D, release/acquire semantics)
__device__ __forceinline__ void csync() {
    asm volatile("barrier.cluster.arrive.aligned;\n\t"
                 "barrier.cluster.wait.aligned;" ::: "memory");
}

// packed f32x2 multiply (sm_100+); max done scalar (no max.f32x2 in PTX)
__device__ __forceinline__ unsigned long long mul2(unsigned long long a, unsigned long long b) {
    unsigned long long r;
    asm("mul.rn.f32x2 %0, %1, %2;" : "=l"(r) : "l"(a), "l"(b));
    return r;
}
__device__ __forceinline__ void unpack2(unsigned long long v, float& lo, float& hi) {
    asm("mov.b64 {%0, %1}, %2;" : "=f"(lo), "=f"(hi) : "l"(v));
}

__device__ __forceinline__ float blk_sum(float v, volatile float* sr) {
    int t = threadIdx.x;
    #pragma unroll
    for (int o = 16; o; o >>= 1) v += __shfl_down_sync(0xFFFFFFFFu, v, o);
    __syncthreads();
    if ((t & 31) == 0) sr[t >> 5] = v;
    __syncthreads();
    if (t < 32) {
        float x = (t < 12) ? sr[t] : 0.f;
        #pragma unroll
        for (int o = 16; o; o >>= 1) x += __shfl_down_sync(0xFFFFFFFFu, x, o);
        if (t == 0) sr[12] = x;
    }
    __syncthreads();
    return sr[12];
}

extern "C" __global__ void __launch_bounds__(NT, 1) __cluster_dims__(NB, 1, 1)
gvae_kernel(const float* __restrict__ X, const int* __restrict__ EI, int E,
            const float* __restrict__ A,
            const float* __restrict__ W1, const float* __restrict__ B1,
            const float* __restrict__ G1, const float* __restrict__ BB1,
            const float* __restrict__ W2, const float* __restrict__ B2,
            const float* __restrict__ G2, const float* __restrict__ BB2,
            const float* __restrict__ MUW, const float* __restrict__ MUB,
            const float* __restrict__ LVW, const float* __restrict__ LVB,
            const float* __restrict__ D1W, const float* __restrict__ D1B,
            const float* __restrict__ D2W, const float* __restrict__ D2B,
            const float* __restrict__ EPS, float* __restrict__ OUT, int osz)
{
    const int bid = blockIdx.x, tid = threadIdx.x;
    const int R0  = bid * RPB;
    const int wrp = tid >> 5, lane = tid & 31;

    __shared__ __align__(16) float uf[4224];          // staging union
    __shared__ __align__(16) float s_x[RPB * NN];     // MPM state rows (1152)
    __shared__ float s_Bd[NN];
    __shared__ int   s_nbr[RPB * 48];
    __shared__ int   s_nnb[RPB];
    __shared__ volatile float s_red[13];

    // ---- S0: zero edge-count matrix ----
    for (int p = bid * NT + tid; p < NN * NN; p += NB * NT) g_cnt[p] = 0;
    csync();

    // ---- S1: scatter edges + self loops; rowmm1 ----
    for (int e = bid * NT + tid; e < E; e += NB * NT)
        atomicAdd(&g_cnt[EI[E + e] * NN + EI[e]], 1);
    if (bid == 0 && tid < NN) atomicAdd(&g_cnt[tid * NN + tid], 1);
    {
        float* s_xin = uf;                            // [RPB][INDIM] = 768
        for (int p = tid; p < RPB * INDIM; p += NT) s_xin[p] = X[R0 * INDIM + p];
        __syncthreads();
        if (tid < HID) {
            int f = tid;
            float acc[RPB];
            #pragma unroll
            for (int r = 0; r < RPB; r++) acc[r] = 0.f;
            #pragma unroll 4
            for (int k4 = 0; k4 < INDIM / 4; k4++) {
                float w0 = W1[(4 * k4 + 0) * HID + f];
                float w1 = W1[(4 * k4 + 1) * HID + f];
                float w2 = W1[(4 * k4 + 2) * HID + f];
                float w3 = W1[(4 * k4 + 3) * HID + f];
                #pragma unroll
                for (int r = 0; r < RPB; r++) {
                    float4 xv = ((const float4*)(s_xin + r * INDIM))[k4];
                    acc[r] += xv.x * w0 + xv.y * w1 + xv.z * w2 + xv.w * w3;
                }
            }
            #pragma unroll
            for (int r = 0; r < RPB; r++) g_tmp1[(R0 + r) * HID + f] = acc[r];
        }
    }
    csync();

    // ---- S2: degrees -> dis; degA ----
    if (wrp < RPB) {
        int n = R0 + wrp;
        float dg = (float)__ldcg(&g_cnt[n * NN + lane])
                 + (float)__ldcg(&g_cnt[n * NN + lane + 32])
                 + (float)__ldcg(&g_cnt[n * NN + lane + 64]);
        #pragma unroll
        for (int o = 16; o; o >>= 1) dg += __shfl_down_sync(0xFFFFFFFFu, dg, o);
        if (lane == 0) g_dis[n] = rsqrtf(dg);
        float dA = A[n * NN + lane] + A[n * NN + lane + 32] + A[n * NN + lane + 64];
        #pragma unroll
        for (int o = 16; o; o >>= 1) dA += __shfl_down_sync(0xFFFFFFFFu, dA, o);
        if (lane == 0) g_degA[n] = dA;
    }
    csync();

    // ---- S3: An rows + agg1 -> g_tmp2T (+B1) ----
    {
        float* s_An = uf + 3072;                      // [RPB][NN] = 1152
        for (int p = tid; p < RPB * NN; p += NT) {
            int r = p / NN, s = p % NN;
            s_An[p] = __ldcg(&g_dis[R0 + r]) * __ldcg(&g_dis[s])
                    * (float)__ldcg(&g_cnt[(R0 + r) * NN + s]);
        }
        __syncthreads();
        if (tid < HID) {
            int f = tid;
            float acc[RPB];
            #pragma unroll
            for (int r = 0; r < RPB; r++) acc[r] = 0.f;
            #pragma unroll 2
            for (int s4 = 0; s4 < NN / 4; s4++) {
                float w0 = __ldcg(&g_tmp1[(4 * s4 + 0) * HID + f]);
                float w1 = __ldcg(&g_tmp1[(4 * s4 + 1) * HID + f]);
                float w2 = __ldcg(&g_tmp1[(4 * s4 + 2) * HID + f]);
                float w3 = __ldcg(&g_tmp1[(4 * s4 + 3) * HID + f]);
                #pragma unroll
                for (int r = 0; r < RPB; r++) {
                    float4 av = ((const float4*)(s_An + r * NN))[s4];
                    acc[r] += av.x * w0 + av.y * w1 + av.z * w2 + av.w * w3;
                }
            }
            float bb = B1[f];
            #pragma unroll
            for (int r = 0; r < RPB; r++) g_tmp2T[f * NN + R0 + r] = acc[r] + bb;
        }
    }
    csync();

    // ---- S4: BN1 + relu ----
    for (int fi = wrp; fi < 32; fi += RPB) {
        int f = bid * 32 + fi;
        const float* col = g_tmp2T + f * NN;
        float v0 = __ldcg(&col[lane]);
        float v1 = __ldcg(&col[lane + 32]);
        float v2 = __ldcg(&col[lane + 64]);
        float s = v0 + v1 + v2;
        #pragma unroll
        for (int o = 16; o; o >>= 1) s += __shfl_xor_sync(0xFFFFFFFFu, s, o);
        float m = s * (1.0f / NN);
        float d0 = v0 - m, d1 = v1 - m, d2 = v2 - m;
        float vv = d0 * d0 + d1 * d1 + d2 * d2;
        #pragma unroll
        for (int o = 16; o; o >>= 1) vv += __shfl_xor_sync(0xFFFFFFFFu, vv, o);
        float sc = G1[f] * rsqrtf(vv * (1.0f / NN) + 1e-5f);
        float bb = BB1[f];
        g_h[lane * HID + f]        = fmaxf(d0 * sc + bb, 0.f);
        g_h[(lane + 32) * HID + f] = fmaxf(d1 * sc + bb, 0.f);
        g_h[(lane + 64) * HID + f] = fmaxf(d2 * sc + bb, 0.f);
    }
    csync();

    // ---- S5: rowmm2 (thread owns feature f; W2 loaded once) ----
    {
        float* s_h = uf;                              // [RPB][HID] = 3072
        for (int p = tid; p < RPB * HID; p += NT) s_h[p] = __ldcg(&g_h[R0 * HID + p]);
        __syncthreads();
        if (tid < HID) {
            int f = tid;
            float acc[RPB];
            #pragma unroll
            for (int r = 0; r < RPB; r++) acc[r] = 0.f;
            #pragma unroll 2
            for (int k4 = 0; k4 < HID / 4; k4++) {
                float w0 = W2[(4 * k4 + 0) * HID + f];
                float w1 = W2[(4 * k4 + 1) * HID + f];
                float w2 = W2[(4 * k4 + 2) * HID + f];
                float w3 = W2[(4 * k4 + 3) * HID + f];
                #pragma unroll
                for (int r = 0; r < RPB; r++) {
                    float4 hv = ((const float4*)(s_h + r * HID))[k4];
                    acc[r] += hv.x * w0 + hv.y * w1 + hv.z * w2 + hv.w * w3;
                }
            }
            #pragma unroll
            for (int r = 0; r < RPB; r++) g_tmp1[(R0 + r) * HID + f] = acc[r];
        }
    }
    csync();

    // ---- S6: agg2 -> g_tmp2T (+B2) ----
    if (tid < HID) {
        const float* s_An = uf + 3072;
        int f = tid;
        float acc[RPB];
        #pragma unroll
        for (int r = 0; r < RPB; r++) acc[r] = 0.f;
        #pragma unroll 2
        for (int s4 = 0; s4 < NN / 4; s4++) {
            float w0 = __ldcg(&g_tmp1[(4 * s4 + 0) * HID + f]);
            float w1 = __ldcg(&g_tmp1[(4 * s4 + 1) * HID + f]);
            float w2 = __ldcg(&g_tmp1[(4 * s4 + 2) * HID + f]);
            float w3 = __ldcg(&g_tmp1[(4 * s4 + 3) * HID + f]);
            #pragma unroll
            for (int r = 0; r < RPB; r++) {
                float4 av = ((const float4*)(s_An + r * NN))[s4];
                acc[r] += av.x * w0 + av.y * w1 + av.z * w2 + av.w * w3;
            }
        }
        float bb = B2[f];
        #pragma unroll
        for (int r = 0; r < RPB; r++) g_tmp2T[f * NN + R0 + r] = acc[r] + bb;
    }
    csync();

    // ---- S7: BN2 + relu + fused sum-pool ----
    for (int fi = wrp; fi < 32; fi += RPB) {
        int f = bid * 32 + fi;
        const float* col = g_tmp2T + f * NN;
        float v0 = __ldcg(&col[lane]);
        float v1 = __ldcg(&col[lane + 32]);
        float v2 = __ldcg(&col[lane + 64]);
        float s = v0 + v1 + v2;
        #pragma unroll
        for (int o = 16; o; o >>= 1) s += __shfl_xor_sync(0xFFFFFFFFu, s, o);
        float m = s * (1.0f / NN);
        float d0 = v0 - m, d1 = v1 - m, d2 = v2 - m;
        float vv = d0 * d0 + d1 * d1 + d2 * d2;
        #pragma unroll
        for (int o = 16; o; o >>= 1) vv += __shfl_xor_sync(0xFFFFFFFFu, vv, o);
        float sc = G2[f] * rsqrtf(vv * (1.0f / NN) + 1e-5f);
        float bb = BB2[f];
        float h0 = fmaxf(d0 * sc + bb, 0.f);
        float h1 = fmaxf(d1 * sc + bb, 0.f);
        float h2 = fmaxf(d2 * sc + bb, 0.f);
        g_h[lane * HID + f]        = h0;
        g_h[(lane + 32) * HID + f] = h1;
        g_h[(lane + 64) * HID + f] = h2;
        float ps = h0 + h1 + h2;
        #pragma unroll
        for (int o = 16; o; o >>= 1) ps += __shfl_down_sync(0xFFFFFFFFu, ps, o);
        if (lane == 0) g_gvec[f] = ps;
    }
    csync();

    // ---- S8: VAE head + dec1 (CTA 0) ----
    if (bid == 0) {
        float* s_g = uf;
        float* s_z = uf + 256;
        if (tid < HID) s_g[tid] = __ldcg(&g_gvec[tid]);
        __syncthreads();
        float klt = 0.f;
        if (tid < ZDIM) {
            float mu = MUB[tid], lv = LVB[tid];
            #pragma unroll 4
            for (int k = 0; k < HID; k++) {
                float gv = s_g[k];
                mu += gv * MUW[k * ZDIM + tid];
                lv += gv * LVW[k * ZDIM + tid];
            }
            s_z[tid] = mu + EPS[tid] * expf(0.5f * lv);
            klt = 1.f + lv - mu * mu - expf(lv);
        }
        float ks = blk_sum(klt, s_red);
        if (tid == 0) g_kl = -0.5f * ks * (1.0f / ZDIM);
        __syncthreads();
        if (tid < HID) {
            float acc = D1B[tid];
            #pragma unroll
            for (int k = 0; k < ZDIM; k++) acc += s_z[k] * D1W[k * HID + tid];
            g_d1[tid] = fmaxf(acc, 0.f);
        }
    }
    csync();

    // ---- S9: dec2 (float4 column groups; 1164 total, ~146/CTA) ----
    {
        float* s_d1 = uf;
        if (tid < HID) s_d1[tid] = __ldcg(&g_d1[tid]);
        __syncthreads();
        int g4 = bid * 146 + tid;
        if (tid < 146 && g4 < TRIN / 4) {
            float4 acc = __ldcg(&((const float4*)D2B)[g4]);
            #pragma unroll 4
            for (int k = 0; k < HID; k++) {
                float dv = s_d1[k];
                float4 w = __ldcg(&((const float4*)D2W)[k * (TRIN / 4) + g4]);
                acc.x += dv * w.x; acc.y += dv * w.y;
                acc.z += dv * w.z; acc.w += dv * w.w;
            }
            ((float4*)g_vecb)[g4] = acc;
        }
    }
    csync();

    // ---- S10: build B, Bd, BCE partials, degB ----
    {
        float rc = 0.f;
        #pragma unroll
        for (int c = 0; c < 3; c++) {
            int p = tid + NT * c;
            int r = p / NN, mcol = p % NN, n = R0 + r;
            int i_ = n < mcol ? n : mcol, j_ = n < mcol ? mcol : n;
            int o = i_ * NN - (i_ * (i_ - 1)) / 2 + (j_ - i_);
            float v = __ldcg(&g_vecb[o]);
            float Bv = 1.f / (1.f + expf(-v));
            g_B[n * NN + mcol] = Bv;
            if (mcol == n) g_Bd[n] = Bv;
            if (mcol >= n)
                rc += fmaxf(v, 0.f) - v * A[n * NN + mcol] + log1pf(expf(-fabsf(v)));
        }
        float rs = blk_sum(rc, s_red);
        if (tid == 0) g_rec[bid] = rs;
        if (wrp < RPB) {
            int n = R0 + wrp;
            float dB = g_B[n * NN + lane] + g_B[n * NN + lane + 32] + g_B[n * NN + lane + 64];
            #pragma unroll
            for (int o = 16; o; o >>= 1) dB += __shfl_down_sync(0xFFFFFFFFu, dB, o);
            if (lane == 0) g_degB[n] = dB;
        }
    }
    csync();

    // ---- MPM setup ----
    if (tid < NN) s_Bd[tid] = __ldcg(&g_Bd[tid]);
    __syncthreads();
    if (wrp < RPB) {
        int n = R0 + wrp, cnt = 0;
        #pragma unroll
        for (int seg = 0; seg < 3; seg++) {
            int m = seg * 32 + lane;
            bool pr = (m != n) && (A[n * NN + m] != 0.f);
            unsigned bal = __ballot_sync(0xFFFFFFFFu, pr);
            if (pr) s_nbr[wrp * 48 + cnt + __popc(bal & ((1u << lane) - 1u))] = m;
            cnt += __popc(bal);
        }
        if (lane == 0) s_nnb[wrp] = cnt;
    }
    float Dv[3];
    #pragma unroll
    for (int c = 0; c < 3; c++) {
        int p = tid + NT * c, r = p / NN, am = p % NN, n = R0 + r;
        Dv[c] = A[n * NN + n] * s_Bd[am]
              / (fabsf(__ldcg(&g_degA[n]) - __ldcg(&g_degB[am])) + 1.f);
    }
    // Q half-row -> packed registers: thread = (b-half hh, column a, row-group gg)
    const int hh = tid & 1, aa = (tid % 192) >> 1, gg = tid / 192;
    unsigned long long qp[24];
    {
        float Bda = s_Bd[aa];
        #pragma unroll
        for (int p = 0; p < 24; p++) {
            int b0 = hh * 48 + 2 * p;
            float q0 = (b0     == aa) ? 0.f : __ldcg(&g_B[aa * NN + b0])     * Bda * s_Bd[b0];
            float q1 = (b0 + 1 == aa) ? 0.f : __ldcg(&g_B[aa * NN + b0 + 1]) * Bda * s_Bd[b0 + 1];
            asm volatile("mov.b64 %0, {%1, %2};" : "=l"(qp[p]) : "f"(q0), "f"(q1));
        }
    }
    for (int p = tid; p < RPB * NN; p += NT) s_x[p] = 1.0f / (float)NN;
    __syncthreads();

    // ---- MPM: 1 csync/iter; packed mul + scalar max; deferred renorm ----
    for (int k = 0; k < ITERS; k++) {
        float* Mb = g_M + (k & 1) * (NN * NN);
        {
            const int rb = 6 * gg;
            float mlo[6], mhi[6];
            #pragma unroll
            for (int r = 0; r < 6; r++) { mlo[r] = 0.f; mhi[r] = 0.f; }
            #pragma unroll
            for (int p4 = 0; p4 < 12; p4++) {
                #pragma unroll
                for (int r = 0; r < 6; r++) {
                    ulonglong2 xv = *((const ulonglong2*)(s_x + (rb + r) * NN + hh * 48) + p4);
                    float l0, h0, l1, h1;
                    unpack2(mul2(qp[2 * p4],     xv.x), l0, h0);
                    unpack2(mul2(qp[2 * p4 + 1], xv.y), l1, h1);
                    mlo[r] = fmaxf(mlo[r], fmaxf(l0, l1));
                    mhi[r] = fmaxf(mhi[r], fmaxf(h0, h1));
                }
            }
            #pragma unroll
            for (int r = 0; r < 6; r++) {
                float m = fmaxf(mlo[r], mhi[r]);
                m = fmaxf(m, __shfl_xor_sync(0xFFFFFFFFu, m, 1));
                if (hh == 0) Mb[(R0 + rb + r) * NN + aa] = m;
            }
        }
        csync();

        float xn[3];
        #pragma unroll
        for (int c = 0; c < 3; c++) {
            int p = tid + NT * c;
            int i = p / NN, am = p % NN;
            int nb = s_nnb[i];
            const int* nl = s_nbr + i * 48;
            float msg = 0.f;
            int j = 0;
            for (; j + 4 <= nb; j += 4)
                msg += __ldcg(&Mb[nl[j] * NN + am]) + __ldcg(&Mb[nl[j + 1] * NN + am])
                     + __ldcg(&Mb[nl[j + 2] * NN + am]) + __ldcg(&Mb[nl[j + 3] * NN + am]);
            for (; j < nb; j++) msg += __ldcg(&Mb[nl[j] * NN + am]);
            xn[c] = s_x[p] * Dv[c] + msg;
        }

        if ((k % 5) == 4) {
            int slot = k / 5;
            float tot = blk_sum(xn[0] * xn[0] + xn[1] * xn[1] + xn[2] * xn[2], s_red);
            if (tid == 0) g_part[slot * NB + bid] = tot;
            if (k == ITERS - 1) {
                csync();
                float s2 = 0.f;
                #pragma unroll
                for (int c = 0; c < NB; c++) s2 += __ldcg(&g_part[slot * NB + c]);
                float invn = rsqrtf(s2);
                int off = (osz > NN * NN) ? (osz - NN * NN) : 0;
                if (osz >= NN * NN) {
                    #pragma unroll
                    for (int c = 0; c < 3; c++) {
                        int p = tid + NT * c;
                        OUT[off + (R0 + p / NN) * NN + (p % NN)] = xn[c] * invn;
                    }
                }
                if (bid == 0 && tid == 0 && (osz < NN * NN || off > 0)) {
                    float rs = 0.f;
                    #pragma unroll
                    for (int c = 0; c < NB; c++) rs += __ldcg(&g_rec[c]);
                    OUT[0] = rs * (1.0f / (float)TRIN) + __ldcg(&g_kl);
                }
                return;
            }
            if (slot > 0) {
                // apply one-checkpoint-stale global norm (exact by homogeneity)
                float s2 = 0.f;
                #pragma unroll
                for (int c = 0; c < NB; c++) s2 += __ldcg(&g_part[(slot - 1) * NB + c]);
                float invn = rsqrtf(s2);
                xn[0] *= invn; xn[1] *= invn; xn[2] *= invn;
            }
        }
        s_x[tid] = xn[0]; s_x[tid + NT] = xn[1]; s_x[tid + 2 * NT] = xn[2];
        __syncthreads();
    }
}

extern "C" void kernel_launch(void* const* d_in, const int* in_sizes, int n_in,
                              void* d_out, int out_size) {
    const float* X   = (const float*)d_in[0];
    const int*   EI  = (const int*)  d_in[1];
    const float* A   = (const float*)d_in[3];
    const float* W1  = (const float*)d_in[4];
    const float* B1  = (const float*)d_in[5];
    const float* G1  = (const float*)d_in[6];
    const float* BB1 = (const float*)d_in[7];
    const float* W2  = (const float*)d_in[8];
    const float* B2  = (const float*)d_in[9];
    const float* G2  = (const float*)d_in[10];
    const float* BB2 = (const float*)d_in[11];
    const float* MUW = (const float*)d_in[12];
    const float* MUB = (const float*)d_in[13];
    const float* LVW = (const float*)d_in[14];
    const float* LVB = (const float*)d_in[15];
    const float* D1W = (const float*)d_in[16];
    const float* D1B = (const float*)d_in[17];
    const float* D2W = (const float*)d_in[18];
    const float* D2B = (const float*)d_in[19];
    const float* EPS = (const float*)d_in[20];
    int E = in_sizes[1] / 2;

    gvae_kernel<<<NB, NT>>>(X, EI, E, A, W1, B1, G1, BB1, W2, B2, G2, BB2,
                            MUW, MUB, LVW, LVB, D1W, D1B, D2W, D2B, EPS,
                            (float*)d_out, out_size);
}

// round 8
// speedup vs baseline: 1.6716x; 1.4549x over previous
#include <cuda_runtime.h>
#include <math.h>

#define NN    96
#define INDIM 64
#define HID   256
#define ZDIM  64
#define TRIN  4656
#define GRIDN 96
#define NT    128
#define ITERS 50
#define MSLOT ((NN + 1) * NN)      // row 96 = permanent zero pad

// ------------- persistent device scratch (no allocations allowed) -------------
__device__ int   g_flag[GRIDN];            // per-block monotonic progress counters
__device__ float g_dis[NN];
__device__ float g_tmp1[NN * HID];
__device__ float g_tmp2[NN * HID];
__device__ float g_h[NN * HID];
__device__ float g_gvec[HID];
__device__ float g_kl;
__device__ __align__(16) float g_vecb[TRIN];
__device__ __align__(16) float g_B[NN * NN];
__device__ float g_Bd[NN];
__device__ float g_degB[NN];
__device__ float g_rec[NN];
__device__ float g_part[10 * NN];          // one slot per 5-iter checkpoint
__device__ float g_M[2 * MSLOT];           // ping-pong; pad row 96 stays zero forever

// ---- release/acquire flag primitives (NO single-address atomics anywhere) ----
__device__ __forceinline__ int ld_acq(const int* p) {
    int v; asm volatile("ld.acquire.gpu.global.s32 %0, [%1];" : "=r"(v) : "l"(p)); return v;
}
__device__ __forceinline__ void st_rel(int* p, int v) {
    asm volatile("st.release.gpu.global.s32 [%0], %1;" :: "l"(p), "r"(v) : "memory");
}

__device__ __forceinline__ void wait_all(int tgt) {
    if (threadIdx.x < 32) {
        for (;;) {
            int ok = 1;
            #pragma unroll
            for (int i = 0; i < 3; i++)
                ok &= (ld_acq(&g_flag[threadIdx.x + 32 * i]) >= tgt);
            if (__all_sync(0xFFFFFFFFu, ok)) break;
        }
    }
    __syncthreads();
}

__device__ __forceinline__ void wait_nbr(const int* s_nbr, int nnb, int tgt) {
    if (threadIdx.x < 32) {
        for (;;) {
            int ok = 1;
            for (int i = threadIdx.x; i < nnb; i += 32)
                ok &= (ld_acq(&g_flag[s_nbr[i]]) >= tgt);
            if (__all_sync(0xFFFFFFFFu, ok)) break;
        }
    }
    __syncthreads();
}

__device__ __forceinline__ void gbar(int base, int& ph) {
    int tgt = base + (++ph);
    __syncthreads();
    if (threadIdx.x == 0) st_rel(&g_flag[blockIdx.x], tgt);
    wait_all(tgt);
}

__device__ __forceinline__ float blk_sum(float v, volatile float* s_w) {
    __syncthreads();
    #pragma unroll
    for (int o = 16; o; o >>= 1) v += __shfl_down_sync(0xFFFFFFFFu, v, o);
    if ((threadIdx.x & 31) == 0) s_w[threadIdx.x >> 5] = v;
    __syncthreads();
    return (s_w[0] + s_w[1]) + (s_w[2] + s_w[3]);
}

extern "C" __global__ void __launch_bounds__(NT, 1)
gvae_kernel(const float* __restrict__ X, const int* __restrict__ EI, int E,
            const float* __restrict__ A,
            const float* __restrict__ W1, const float* __restrict__ B1,
            const float* __restrict__ G1, const float* __restrict__ BB1,
            const float* __restrict__ W2, const float* __restrict__ B2,
            const float* __restrict__ G2, const float* __restrict__ BB2,
            const float* __restrict__ MUW, const float* __restrict__ MUB,
            const float* __restrict__ LVW, const float* __restrict__ LVB,
            const float* __restrict__ D1W, const float* __restrict__ D1B,
            const float* __restrict__ D2W, const float* __restrict__ D2B,
            const float* __restrict__ EPS, float* __restrict__ OUT, int osz)
{
    const int bid = blockIdx.x, tid = threadIdx.x;
    __shared__ int   s_cnt[NN];
    __shared__ float s_An[NN];
    __shared__ float s_row[HID];
    __shared__ float s_mu[NT], s_lv[NT];
    __shared__ float s_z[ZDIM];
    __shared__ float s_d1[HID];
    __shared__ __align__(16) float4 s_dec[104];
    __shared__ __align__(16) float s_x[NN];
    __shared__ __align__(16) float s_Bd[NN];
    __shared__ int   s_nbr[NN + 8];
    __shared__ int   s_wcnt[4];
    __shared__ int   s_cnt2[2];
    __shared__ volatile float s_w[4];
    __shared__ float s_degA;

    int base = ld_acq(&g_flag[bid]);
    int ph = 0;

    // ==== S0: own-row edge count (no global scatter), deg->dis, degA, rowmm1 ====
    if (tid < NN) s_cnt[tid] = 0;
    if (tid < INDIM) s_row[tid] = X[bid * INDIM + tid];
    __syncthreads();
    for (int e = tid; e < E; e += NT)
        if (EI[E + e] == bid) atomicAdd(&s_cnt[EI[e]], 1);
    __syncthreads();
    if (tid == 0) s_cnt[bid] += 1;                     // self loop
    __syncthreads();
    {
        float dg = blk_sum((tid < NN) ? (float)s_cnt[tid] : 0.f, s_w);
        float dA = blk_sum((tid < NN) ? A[bid * NN + tid] : 0.f, s_w);
        if (tid == 0) { g_dis[bid] = rsqrtf(dg); s_degA = dA; }
    }
    {
        int f0 = tid, f1 = tid + NT;
        float a0 = 0.f, a1 = 0.f;
        #pragma unroll 8
        for (int k = 0; k < INDIM; k++) {
            float xv = s_row[k];
            a0 += xv * W1[k * HID + f0];
            a1 += xv * W1[k * HID + f1];
        }
        g_tmp1[bid * HID + f0] = a0;
        g_tmp1[bid * HID + f1] = a1;
    }
    gbar(base, ph);                                    // 1

    // ==== S2: An row + agg1 (+B1) ====
    {
        float db = __ldcg(&g_dis[bid]);
        if (tid < NN) s_An[tid] = db * __ldcg(&g_dis[tid]) * (float)s_cnt[tid];
    }
    __syncthreads();
    {
        int f0 = tid, f1 = tid + NT;
        float a0 = 0.f, a1 = 0.f;
        #pragma unroll 8
        for (int s = 0; s < NN; s++) {
            float an = s_An[s];
            a0 += an * __ldcg(&g_tmp1[s * HID + f0]);
            a1 += an * __ldcg(&g_tmp1[s * HID + f1]);
        }
        g_tmp2[bid * HID + f0] = B1[f0] + a0;
        g_tmp2[bid * HID + f1] = B1[f1] + a1;
    }
    gbar(base, ph);                                    // 2

    // ==== S3: BN1 + relu ====
    for (int f = bid; f < HID; f += GRIDN) {
        float v   = (tid < NN) ? __ldcg(&g_tmp2[tid * HID + f]) : 0.f;
        float m   = blk_sum(v, s_w) * (1.0f / NN);
        float d   = (tid < NN) ? v - m : 0.f;
        float var = blk_sum(d * d, s_w) * (1.0f / NN);
        float sc  = G1[f] * rsqrtf(var + 1e-5f);
        if (tid < NN) g_h[tid * HID + f] = fmaxf(d * sc + BB1[f], 0.f);
    }
    gbar(base, ph);                                    // 3

    // ==== S4: rowmm2 ====
    for (int k = tid; k < HID; k += NT) s_row[k] = __ldcg(&g_h[bid * HID + k]);
    __syncthreads();
    {
        int f0 = tid, f1 = tid + NT;
        float a0 = 0.f, a1 = 0.f;
        #pragma unroll 8
        for (int k = 0; k < HID; k++) {
            float hv = s_row[k];
            a0 += hv * W2[k * HID + f0];
            a1 += hv * W2[k * HID + f1];
        }
        g_tmp1[bid * HID + f0] = a0;
        g_tmp1[bid * HID + f1] = a1;
    }
    gbar(base, ph);                                    // 4

    // ==== S5: agg2 (+B2) ====
    {
        int f0 = tid, f1 = tid + NT;
        float a0 = 0.f, a1 = 0.f;
        #pragma unroll 8
        for (int s = 0; s < NN; s++) {
            float an = s_An[s];
            a0 += an * __ldcg(&g_tmp1[s * HID + f0]);
            a1 += an * __ldcg(&g_tmp1[s * HID + f1]);
        }
        g_tmp2[bid * HID + f0] = B2[f0] + a0;
        g_tmp2[bid * HID + f1] = B2[f1] + a1;
    }
    gbar(base, ph);                                    // 5

    // ==== S6: BN2 + relu + fused sum-pool ====
    for (int f = bid; f < HID; f += GRIDN) {
        float v   = (tid < NN) ? __ldcg(&g_tmp2[tid * HID + f]) : 0.f;
        float m   = blk_sum(v, s_w) * (1.0f / NN);
        float d   = (tid < NN) ? v - m : 0.f;
        float var = blk_sum(d * d, s_w) * (1.0f / NN);
        float sc  = G2[f] * rsqrtf(var + 1e-5f);
        float hv  = (tid < NN) ? fmaxf(d * sc + BB2[f], 0.f) : 0.f;
        if (tid < NN) g_h[tid * HID + f] = hv;
        float ps = blk_sum(hv, s_w);
        if (tid == 0) g_gvec[f] = ps;
    }
    gbar(base, ph);                                    // 6

    // ==== S7: VAE head replicated in EVERY block (bit-identical) + dec1 + dec2 ====
    for (int k = tid; k < HID; k += NT) s_row[k] = __ldcg(&g_gvec[k]);
    __syncthreads();
    {
        int z = tid & 63, h = tid >> 6;               // k-half split -> 2x MLP
        float amu = 0.f, alv = 0.f;
        #pragma unroll 8
        for (int k = h * 128; k < h * 128 + 128; k++) {
            float gv = s_row[k];
            amu += gv * MUW[k * ZDIM + z];
            alv += gv * LVW[k * ZDIM + z];
        }
        s_mu[tid] = amu; s_lv[tid] = alv;
    }
    __syncthreads();
    float klt = 0.f;
    if (tid < ZDIM) {
        float mu = s_mu[tid] + s_mu[tid + 64] + MUB[tid];
        float lv = s_lv[tid] + s_lv[tid + 64] + LVB[tid];
        s_z[tid] = mu + EPS[tid] * expf(0.5f * lv);
        klt = 1.f + lv - mu * mu - expf(lv);
    }
    {
        float ks = blk_sum(klt, s_w);
        if (bid == 0 && tid == 0) g_kl = -0.5f * ks * (1.0f / ZDIM);
    }
    __syncthreads();
    {
        int f0 = tid, f1 = tid + NT;
        float a0 = D1B[f0], a1 = D1B[f1];
        #pragma unroll 8
        for (int k = 0; k < ZDIM; k++) {
            float zv = s_z[k];
            a0 += zv * D1W[k * HID + f0];
            a1 += zv * D1W[k * HID + f1];
        }
        s_d1[f0] = fmaxf(a0, 0.f);
        s_d1[f1] = fmaxf(a1, 0.f);
    }
    __syncthreads();
    // dec2: this block's float4 output groups, k split 8 ways for MLP
    {
        const int ng = (bid < 12) ? 13 : 12;
        const int g0 = bid * 12 + (bid < 12 ? bid : 12);
        if (tid < ng * 8) {
            int grp = tid >> 3, kq = tid & 7;
            int g4 = g0 + grp;
            const float4* W4 = (const float4*)D2W;
            float ax = 0.f, ay = 0.f, az = 0.f, aw = 0.f;
            #pragma unroll 8
            for (int k = kq * 32; k < kq * 32 + 32; k++) {
                float dv = s_d1[k];
                float4 w = __ldcg(&W4[k * (TRIN / 4) + g4]);
                ax += dv * w.x; ay += dv * w.y; az += dv * w.z; aw += dv * w.w;
            }
            s_dec[tid] = make_float4(ax, ay, az, aw);
        }
        __syncthreads();
        if (tid < ng) {
            float4 a = s_dec[tid * 8];
            #pragma unroll
            for (int j = 1; j < 8; j++) {
                float4 b = s_dec[tid * 8 + j];
                a.x += b.x; a.y += b.y; a.z += b.z; a.w += b.w;
            }
            float4 bb = __ldcg(&((const float4*)D2B)[g0 + tid]);
            a.x += bb.x; a.y += bb.y; a.z += bb.z; a.w += bb.w;
            ((float4*)g_vecb)[g0 + tid] = a;
        }
    }
    gbar(base, ph);                                    // 7

    // ==== S8: build B row, Bd, degB, BCE partial ====
    {
        float Bv = 0.f, rc = 0.f;
        if (tid < NN) {
            int i_ = bid < tid ? bid : tid;
            int j_ = bid < tid ? tid : bid;
            int o  = i_ * NN - (i_ * (i_ - 1)) / 2 + (j_ - i_);
            float v = __ldcg(&g_vecb[o]);
            Bv = 1.f / (1.f + expf(-v));
            g_B[bid * NN + tid] = Bv;
            if (tid == bid) g_Bd[bid] = Bv;
            if (tid >= bid) {
                float truth = A[bid * NN + tid];
                rc = fmaxf(v, 0.f) - v * truth + log1pf(expf(-fabsf(v)));
            }
        }
        float dB = blk_sum(Bv, s_w);
        float rs = blk_sum(rc, s_w);
        if (tid == 0) { g_degB[bid] = dB; g_rec[bid] = rs; }
    }
    gbar(base, ph);                                    // 8  (== F0)

    // ==== MPM setup: Q row -> float4 regs, D, deterministic neighbor list ====
    if (tid < NN) s_Bd[tid] = __ldcg(&g_Bd[tid]);
    {
        bool pred = (tid < NN) && (tid != bid) && (A[bid * NN + tid] != 0.f);
        unsigned mm = __ballot_sync(0xFFFFFFFFu, pred);
        int w = tid >> 5, lane = tid & 31;
        if (lane == 0) s_wcnt[w] = __popc(mm);
        __syncthreads();
        int bpos = 0;
        if (w > 0) bpos += s_wcnt[0];
        if (w > 1) bpos += s_wcnt[1];
        if (w > 2) bpos += s_wcnt[2];
        if (pred) s_nbr[bpos + __popc(mm & ((1u << lane) - 1u))] = tid;
        __syncthreads();
        if (tid == 0) {
            int c = s_wcnt[0] + s_wcnt[1] + s_wcnt[2] + s_wcnt[3];
            s_cnt2[0] = c;
            while (c & 7) s_nbr[c++] = NN;             // pad -> zero row of M
            s_cnt2[1] = c;
        }
    }
    __syncthreads();
    const int nnb = s_cnt2[0];
    const int nn8 = s_cnt2[1];

    float4 q4[24];
    float  Da = 0.f;
    if (tid < NN) {
        float Bda = s_Bd[tid];
        Da = A[bid * NN + bid] * Bda /
             (fabsf(s_degA - __ldcg(&g_degB[tid])) + 1.f);
        const float4* br  = (const float4*)(g_B + tid * NN);
        const float4* sd4 = (const float4*)s_Bd;
        #pragma unroll
        for (int b4 = 0; b4 < 24; b4++) {
            float4 bv = __ldcg(&br[b4]);
            float4 sd = sd4[b4];
            int b = 4 * b4;
            float4 qv;
            qv.x = (b + 0 == tid) ? 0.f : bv.x * Bda * sd.x;
            qv.y = (b + 1 == tid) ? 0.f : bv.y * Bda * sd.y;
            qv.z = (b + 2 == tid) ? 0.f : bv.z * Bda * sd.z;
            qv.w = (b + 3 == tid) ? 0.f : bv.w * Bda * sd.w;
            q4[b4] = qv;
        }
        s_x[tid] = 1.0f / (float)NN;
    }
    __syncthreads();

    // ==== MPM: ONE bump + neighbor-wait per iter; stale-by-2 renorm ====
    for (int k = 0; k < ITERS; k++) {
        float* Mb = g_M + (k & 1) * MSLOT;
        // phase A: M[bid, a=tid] = max_b Q[a,b] * x[bid,b]
        if (tid < NN) {
            const float4* sx4 = (const float4*)s_x;
            float m0 = 0.f, m1 = 0.f, m2 = 0.f, m3 = 0.f;
            #pragma unroll
            for (int b4 = 0; b4 < 24; b4++) {
                float4 xv = sx4[b4];
                float4 qv = q4[b4];
                m0 = fmaxf(m0, qv.x * xv.x);
                m1 = fmaxf(m1, qv.y * xv.y);
                m2 = fmaxf(m2, qv.z * xv.z);
                m3 = fmaxf(m3, qv.w * xv.w);
            }
            Mb[bid * NN + tid] = fmaxf(fmaxf(m0, m1), fmaxf(m2, m3));
        }
        __syncthreads();
        int tgt = base + (++ph);
        if (tid == 0) st_rel(&g_flag[bid], tgt);
        wait_nbr(s_nbr, nnb, tgt);

        // phase B
        float xn = 0.f;
        if (tid < NN) {
            float msg = 0.f;
            for (int j = 0; j < nn8; j += 8) {
                float t0 = __ldcg(&Mb[s_nbr[j + 0] * NN + tid]);
                float t1 = __ldcg(&Mb[s_nbr[j + 1] * NN + tid]);
                float t2 = __ldcg(&Mb[s_nbr[j + 2] * NN + tid]);
                float t3 = __ldcg(&Mb[s_nbr[j + 3] * NN + tid]);
                float t4 = __ldcg(&Mb[s_nbr[j + 4] * NN + tid]);
                float t5 = __ldcg(&Mb[s_nbr[j + 5] * NN + tid]);
                float t6 = __ldcg(&Mb[s_nbr[j + 6] * NN + tid]);
                float t7 = __ldcg(&Mb[s_nbr[j + 7] * NN + tid]);
                msg += ((t0 + t1) + (t2 + t3)) + ((t4 + t5) + (t6 + t7));
            }
            xn = s_x[tid] * Da + msg;
        }

        if ((k % 5) == 4) {
            int r = k / 5;
            float p = blk_sum(xn * xn, s_w);
            if (tid == 0) g_part[r * NN + bid] = p;
            if (k == ITERS - 1) {
                __syncthreads();
                int ft = base + (++ph);
                if (tid == 0) st_rel(&g_flag[bid], ft);
                wait_all(ft);
                float pv   = (tid < NN) ? __ldcg(&g_part[9 * NN + tid]) : 0.f;
                float invn = rsqrtf(blk_sum(pv, s_w));
                int off = (osz > NN * NN) ? (osz - NN * NN) : 0;
                if (osz >= NN * NN && tid < NN)
                    OUT[off + bid * NN + tid] = xn * invn;
                if (bid == 0) {
                    float rp = (tid < NN) ? __ldcg(&g_rec[tid]) : 0.f;
                    float rs = blk_sum(rp, s_w);
                    if (tid == 0 && (osz < NN * NN || off > 0))
                        OUT[0] = rs * (1.0f / (float)TRIN) + __ldcg(&g_kl);
                }
                return;
            }
            if (r >= 2) {
                // stale-by-2 renorm: exact via homogeneity; visible via 10-hop chains
                float pv   = (tid < NN) ? __ldcg(&g_part[(r - 2) * NN + tid]) : 0.f;
                float invn = rsqrtf(blk_sum(pv, s_w));
                xn *= invn;
            }
        }
        if (tid < NN) s_x[tid] = xn;
        __syncthreads();
    }
}

extern "C" void kernel_launch(void* const* d_in, const int* in_sizes, int n_in,
                              void* d_out, int out_size) {
    const float* X   = (const float*)d_in[0];
    const int*   EI  = (const int*)  d_in[1];
    const float* A   = (const float*)d_in[3];
    const float* W1  = (const float*)d_in[4];
    const float* B1  = (const float*)d_in[5];
    const float* G1  = (const float*)d_in[6];
    const float* BB1 = (const float*)d_in[7];
    const float* W2  = (const float*)d_in[8];
    const float* B2  = (const float*)d_in[9];
    const float* G2  = (const float*)d_in[10];
    const float* BB2 = (const float*)d_in[11];
    const float* MUW = (const float*)d_in[12];
    const float* MUB = (const float*)d_in[13];
    const float* LVW = (const float*)d_in[14];
    const float* LVB = (const float*)d_in[15];
    const float* D1W = (const float*)d_in[16];
    const float* D1B = (const float*)d_in[17];
    const float* D2W = (const float*)d_in[18];
    const float* D2B = (const float*)d_in[19];
    const float* EPS = (const float*)d_in[20];
    int E = in_sizes[1] / 2;

    gvae_kernel<<<GRIDN, NT>>>(X, EI, E, A, W1, B1, G1, BB1, W2, B2, G2, BB2,
                               MUW, MUB, LVW, LVB, D1W, D1B, D2W, D2B, EPS,
                               (float*)d_out, out_size);
}